// round 15
// baseline (speedup 1.0000x reference)
#include <cuda_runtime.h>
#include <cuda_bf16.h>
#include <cstdint>

#define BB 16
#define CIN 3
#define HH 256
#define WW 256
#define COUT 64
#define NPIX (BB*HH*WW)
#define PLANE (HH*WW)
#define NBLKP (BB*HH/2)           // 2048 two-row blocks
#define NSLOT (NBLKP*8)           // 16384 per-warp BN slots

// BN partials: [slot][channel] (coalesced per-warp stores)
__device__ float g_partS2[NSLOT*64];
__device__ float g_partQ2[NSLOT*64];
__device__ float g_scale[COUT];
__device__ float g_shift[COUT];

// Pre-packed MMA A-fragments (filled by prep_kernel each launch)
__device__ float4 g_wfragA[7*4*32];   // main GEMM  [kt][m][lane]
__device__ float4 g_wfragO[4*2*32];   // offset GEMM [kt][m][lane]

// ---- dynamic SMEM layout (bytes, 16B aligned) ----
#define TAP_STRIDE 264
#define OFF_WA    0                               // float4[896]       14336
#define OFF_TAPS  (OFF_WA + 896*16)               // float[56][264]    59136
#define OFF_X     (OFF_TAPS + 56*TAP_STRIDE*4)    // float[3][4][264]  12672
#define OFF_OFFW  (OFF_X + 3*4*264*4)             // float[8][18][32]  18432
#define OFF_WOFFA (OFF_OFFW + 8*18*32*4)          // float4[256]        4096
#define OFF_BIAS  (OFF_WOFFA + 256*16)            // float[64]           256
#define SMEM_BYTES (OFF_BIAS + 64*4)              // = 108928

__device__ __forceinline__ float tf32r(float f) {
    unsigned u; asm("cvt.rna.tf32.f32 %0, %1;" : "=r"(u) : "f"(f));
    return __uint_as_float(u);
}
__device__ __forceinline__ void mma_tf32(float* d, const unsigned* a, const unsigned* b) {
    asm("mma.sync.aligned.m16n8k8.row.col.f32.tf32.tf32.f32 "
        "{%0,%1,%2,%3}, {%4,%5,%6,%7}, {%8,%9}, {%0,%1,%2,%3};"
        : "+f"(d[0]), "+f"(d[1]), "+f"(d[2]), "+f"(d[3])
        : "r"(a[0]), "r"(a[1]), "r"(a[2]), "r"(a[3]), "r"(b[0]), "r"(b[1]));
}

// ---------------------------------------------------------------------------
// Prep: pack weights into fragment order
// ---------------------------------------------------------------------------
__global__ void prep_kernel(const float* __restrict__ w_off,
                            const float* __restrict__ w_dcn,
                            const float* __restrict__ w_conv)
{
    const int i = blockIdx.x * 256 + threadIdx.x;
    if (i < 3584) {
        int j    = i & 3;
        int lane = (i >> 2) & 31;
        int m    = (i >> 7) & 3;
        int kt   = i >> 9;
        int gg   = lane >> 2, qq = lane & 3;
        int c = m*16 + gg + ((j & 1) << 3);
        int k = kt*8 + qq + ((j >> 1) << 2);
        float v = 0.f;
        if (k < 27)      v = w_conv[c*27 + k];
        else if (k < 54) v = w_dcn[c*27 + (k - 27)];
        reinterpret_cast<float*>(g_wfragA)[i] = tf32r(v);
    }
    if (i < 1024) {
        int j    = i & 3;
        int lane = (i >> 2) & 31;
        int m    = (i >> 7) & 1;
        int kt   = i >> 8;
        int gg   = lane >> 2, qq = lane & 3;
        int c = m*16 + gg + ((j & 1) << 3);
        int k = kt*8 + qq + ((j >> 1) << 2);
        float v = 0.f;
        if (c < 18 && k < 27) v = w_off[c*27 + k];
        reinterpret_cast<float*>(g_wfragO)[i] = tf32r(v);
    }
}

// ---------------------------------------------------------------------------
// Kernel A: 2 rows per block; stage once, loop the warp-local pipeline twice.
// BN partials accumulate in registers, written once per warp (no barriers).
// ---------------------------------------------------------------------------
__global__ __launch_bounds__(256, 2)
void fused_main(const float* __restrict__ x,
                const float* __restrict__ b_off,
                const float* __restrict__ b_conv,
                float* __restrict__ out)
{
    extern __shared__ __align__(16) char smem[];
    float4* s_wA    = (float4*)(smem + OFF_WA);
    float*  s_taps  = (float*)(smem + OFF_TAPS);
    float*  s_x     = (float*)(smem + OFF_X);      // [ci][4 rows][264]
    float*  s_offw  = (float*)(smem + OFF_OFFW);
    float4* s_woffA = (float4*)(smem + OFF_WOFFA);
    float*  s_bias  = (float*)(smem + OFF_BIAS);
    __shared__ float s_boff[18];

    const int tid  = threadIdx.x;
    const int bidx = blockIdx.x;
    const int b    = bidx >> 7;
    const int h0   = (bidx & 127) << 1;

    // ---- weight staging (once) ----
    {
        #pragma unroll
        for (int r = 0; r < 4; r++) {
            int i = r*256 + tid;
            if (i < 896) s_wA[i] = g_wfragA[i];
        }
        s_woffA[tid] = g_wfragO[tid];
    }
    // zero tap rows 27..31 and 54..55 (once; never overwritten)
    {
        float4* t1 = reinterpret_cast<float4*>(s_taps + 27*TAP_STRIDE);
        for (int i = tid; i < (5*TAP_STRIDE)/4; i += 256) t1[i] = make_float4(0.f,0.f,0.f,0.f);
        float4* t2 = reinterpret_cast<float4*>(s_taps + 54*TAP_STRIDE);
        if (tid < (2*TAP_STRIDE)/4) t2[tid] = make_float4(0.f,0.f,0.f,0.f);
    }
    if (tid < 64) s_bias[tid] = b_conv[tid];
    if (tid < 18) s_boff[tid] = b_off[tid];

    // ---- x staging: 4 rows (h0-1..h0+2) x 3 ch, thread-strided ----
    {
        const float* xb = x + (size_t)b * 3 * PLANE;
        for (int i = tid; i < 3*4*258; i += 256) {
            int ci = i / (4*258);
            int r  = (i / 258) & 3;
            int cc = i - (i / 258) * 258;
            int gy = h0 - 1 + r;
            int gx = cc - 1;
            float v = 0.f;
            if (gy >= 0 && gy < HH && gx >= 0 && gx < WW)
                v = xb[(size_t)ci*PLANE + gy*WW + gx];
            s_x[(ci*4 + r)*264 + cc] = v;
        }
    }
    __syncthreads();   // the ONLY block-wide sync

    const int wid  = tid >> 5;
    const int lane = tid & 31;
    const int g    = lane >> 2;
    const int q    = lane & 3;
    const int pxw  = wid << 5;
    float* offw    = s_offw + wid * (18*32);

    // BN register accumulators across both rows
    float bnS0[4] = {0,0,0,0}, bnS1[4] = {0,0,0,0};
    float bnQ0[4] = {0,0,0,0}, bnQ1[4] = {0,0,0,0};

    #pragma unroll 1
    for (int r2 = 0; r2 < 2; r2++) {
        const int h = h0 + r2;

        // ---- im2col: thread w writes tf32 tap column w, rows 0..26 ----
        {
            const int w = tid;
            #pragma unroll
            for (int ci = 0; ci < 3; ci++)
                #pragma unroll
                for (int k = 0; k < 9; k++)
                    s_taps[(ci*9 + k)*TAP_STRIDE + w] =
                        tf32r(s_x[(ci*4 + r2 + k/3)*264 + w + (k%3)]);
        }
        __syncwarp();

        // ================= Offset conv MMA (warp-local) =================
        {
            float Co[2][4][4];
            #pragma unroll
            for (int m = 0; m < 2; m++)
                #pragma unroll
                for (int n = 0; n < 4; n++)
                    #pragma unroll
                    for (int r = 0; r < 4; r++) Co[m][n][r] = 0.f;

            #pragma unroll
            for (int kt = 0; kt < 4; kt++) {
                const int kb = kt << 3;
                unsigned A[2][4];
                #pragma unroll
                for (int m = 0; m < 2; m++) {
                    float4 af = s_woffA[(kt*2 + m)*32 + lane];
                    A[m][0] = __float_as_uint(af.x);
                    A[m][1] = __float_as_uint(af.y);
                    A[m][2] = __float_as_uint(af.z);
                    A[m][3] = __float_as_uint(af.w);
                }
                unsigned Bf[4][2];
                #pragma unroll
                for (int n = 0; n < 4; n++) {
                    const float* bp = s_taps + (kb + q)*TAP_STRIDE + pxw + (n << 3) + g;
                    Bf[n][0] = __float_as_uint(bp[0]);
                    Bf[n][1] = __float_as_uint(bp[4*TAP_STRIDE]);
                }
                #pragma unroll
                for (int m = 0; m < 2; m++)
                    #pragma unroll
                    for (int n = 0; n < 4; n++)
                        mma_tf32(Co[m][n], A[m], Bf[n]);
            }

            #pragma unroll
            for (int n = 0; n < 4; n++) {
                const int cw = (n << 3) + (q << 1);
                *reinterpret_cast<float2*>(offw + g*32 + cw)
                    = make_float2(Co[0][n][0], Co[0][n][1]);
                *reinterpret_cast<float2*>(offw + (g+8)*32 + cw)
                    = make_float2(Co[0][n][2], Co[0][n][3]);
                if (g < 2)
                    *reinterpret_cast<float2*>(offw + (16+g)*32 + cw)
                        = make_float2(Co[1][n][0], Co[1][n][1]);
            }
        }
        __syncwarp();

        // ================= Gathers: deform taps rows 27..53 ================
        {
            const int w = tid;
            const float* xb = x + (size_t)b * 3 * PLANE;
            #pragma unroll
            for (int k = 0; k < 9; k++) {
                float dy = offw[(2*k)*32 + lane]   + s_boff[2*k];
                float dx = offw[(2*k+1)*32 + lane] + s_boff[2*k+1];
                const int ky = k / 3, kx = k - 3*ky;
                float py = (float)(h + ky - 1) + dy;
                float px = (float)(w + kx - 1) + dx;
                float y0 = floorf(py), x0 = floorf(px);
                float ly = py - y0,    lx = px - x0;
                float hy = 1.f - ly,   hx = 1.f - lx;
                float y1 = y0 + 1.f,   x1 = x0 + 1.f;
                bool vy0 = (y0 >= 0.f) && (y0 <= 255.f);
                bool vy1 = (y1 >= 0.f) && (y1 <= 255.f);
                bool vx0 = (x0 >= 0.f) && (x0 <= 255.f);
                bool vx1 = (x1 >= 0.f) && (x1 <= 255.f);
                float w00 = hy*hx * ((vy0 && vx0) ? 1.f : 0.f);
                float w01 = hy*lx * ((vy0 && vx1) ? 1.f : 0.f);
                float w10 = ly*hx * ((vy1 && vx0) ? 1.f : 0.f);
                float w11 = ly*lx * ((vy1 && vx1) ? 1.f : 0.f);
                int iy0 = min(max((int)y0, 0), 255);
                int iy1 = min(max((int)y1, 0), 255);
                int ix0 = min(max((int)x0, 0), 255);
                int ix1 = min(max((int)x1, 0), 255);
                int i00 = iy0*WW + ix0, i01 = iy0*WW + ix1;
                int i10 = iy1*WW + ix0, i11 = iy1*WW + ix1;
                #pragma unroll
                for (int ci = 0; ci < 3; ci++) {
                    const float* xc = xb + ci * PLANE;
                    float tap = w00 * __ldg(xc + i00) + w01 * __ldg(xc + i01)
                              + w10 * __ldg(xc + i10) + w11 * __ldg(xc + i11);
                    s_taps[(27 + ci*9 + k)*TAP_STRIDE + w] = tf32r(tap);
                }
            }
        }
        __syncwarp();

        // ================= Main tensor-core GEMM (warp-local) ==============
        float C[4][4][4];
        #pragma unroll
        for (int m = 0; m < 4; m++)
            #pragma unroll
            for (int n = 0; n < 4; n++)
                #pragma unroll
                for (int r = 0; r < 4; r++) C[m][n][r] = 0.f;

        #pragma unroll
        for (int kt = 0; kt < 7; kt++) {
            const int kb = kt << 3;
            unsigned A[4][4];
            #pragma unroll
            for (int m = 0; m < 4; m++) {
                float4 af = s_wA[(kt*4 + m)*32 + lane];
                A[m][0] = __float_as_uint(af.x);
                A[m][1] = __float_as_uint(af.y);
                A[m][2] = __float_as_uint(af.z);
                A[m][3] = __float_as_uint(af.w);
            }
            unsigned Bf[4][2];
            #pragma unroll
            for (int n = 0; n < 4; n++) {
                const float* bp = s_taps + (kb + q)*TAP_STRIDE + pxw + (n << 3) + g;
                Bf[n][0] = __float_as_uint(bp[0]);
                Bf[n][1] = __float_as_uint(bp[4*TAP_STRIDE]);
            }
            #pragma unroll
            for (int m = 0; m < 4; m++)
                #pragma unroll
                for (int n = 0; n < 4; n++)
                    mma_tf32(C[m][n], A[m], Bf[n]);
        }

        // ---- epilogue: bias, store, BN register accumulation ----
        float* outbh = out + (size_t)b * COUT * PLANE + (size_t)h * WW;
        #pragma unroll
        for (int m = 0; m < 4; m++) {
            const int ch0 = m*16 + g;
            const int ch1 = ch0 + 8;
            const float b0v = s_bias[ch0];
            const float b1v = s_bias[ch1];
            float s0 = 0.f, q0 = 0.f, s1 = 0.f, q1 = 0.f;
            #pragma unroll
            for (int n = 0; n < 4; n++) {
                float c0 = C[m][n][0] + b0v, c1 = C[m][n][1] + b0v;
                float c2 = C[m][n][2] + b1v, c3 = C[m][n][3] + b1v;
                const int px = pxw + (n << 3) + (q << 1);
                *reinterpret_cast<float2*>(outbh + (size_t)ch0 * PLANE + px) = make_float2(c0, c1);
                *reinterpret_cast<float2*>(outbh + (size_t)ch1 * PLANE + px) = make_float2(c2, c3);
                s0 += c0 + c1;  q0 += c0*c0 + c1*c1;
                s1 += c2 + c3;  q1 += c2*c2 + c3*c3;
            }
            #pragma unroll
            for (int d = 1; d < 4; d <<= 1) {
                s0 += __shfl_xor_sync(0xffffffffu, s0, d);
                q0 += __shfl_xor_sync(0xffffffffu, q0, d);
                s1 += __shfl_xor_sync(0xffffffffu, s1, d);
                q1 += __shfl_xor_sync(0xffffffffu, q1, d);
            }
            bnS0[m] += s0;  bnQ0[m] += q0;
            bnS1[m] += s1;  bnQ1[m] += q1;
        }
    }

    // ---- per-warp BN partial store (one 64-channel slot, coalesced) ----
    if (q == 0) {
        float* slotS = g_partS2 + ((size_t)bidx*8 + wid)*64;
        float* slotQ = g_partQ2 + ((size_t)bidx*8 + wid)*64;
        #pragma unroll
        for (int m = 0; m < 4; m++) {
            slotS[m*16 + g]     = bnS0[m];
            slotS[m*16 + g + 8] = bnS1[m];
            slotQ[m*16 + g]     = bnQ0[m];
            slotQ[m*16 + g + 8] = bnQ1[m];
        }
    }
}

// ---------------------------------------------------------------------------
// Kernel B: stats reduce + finalize (16 blocks x 4 channels)
// ---------------------------------------------------------------------------
__global__ __launch_bounds__(256)
void stats_all(const float* __restrict__ gamma,
               const float* __restrict__ beta)
{
    const int cb  = blockIdx.x * 4;   // channels cb..cb+3
    const int tid = threadIdx.x;
    float4 aS = make_float4(0.f,0.f,0.f,0.f);
    float4 aQ = make_float4(0.f,0.f,0.f,0.f);
    for (int i = tid; i < NSLOT; i += 256) {
        float4 vs = *reinterpret_cast<const float4*>(g_partS2 + (size_t)i*64 + cb);
        float4 vq = *reinterpret_cast<const float4*>(g_partQ2 + (size_t)i*64 + cb);
        aS.x += vs.x; aS.y += vs.y; aS.z += vs.z; aS.w += vs.w;
        aQ.x += vq.x; aQ.y += vq.y; aQ.z += vq.z; aQ.w += vq.w;
    }
    __shared__ float4 sS[256], sQ[256];
    sS[tid] = aS; sQ[tid] = aQ;
    __syncthreads();
    for (int st = 128; st > 0; st >>= 1) {
        if (tid < st) {
            float4 xs = sS[tid+st], xq = sQ[tid+st];
            float4 ys = sS[tid],    yq = sQ[tid];
            ys.x += xs.x; ys.y += xs.y; ys.z += xs.z; ys.w += xs.w;
            yq.x += xq.x; yq.y += xq.y; yq.z += xq.z; yq.w += xq.w;
            sS[tid] = ys; sQ[tid] = yq;
        }
        __syncthreads();
    }
    if (tid < 4) {
        float s = reinterpret_cast<const float*>(&sS[0])[tid];
        float q = reinterpret_cast<const float*>(&sQ[0])[tid];
        const float invN = 1.f / (float)NPIX;
        float mean = s * invN;
        float var  = q * invN - mean * mean;
        float inv  = rsqrtf(var + 1e-5f);
        float sc   = gamma[cb + tid] * inv;
        g_scale[cb + tid] = sc;
        g_shift[cb + tid] = beta[cb + tid] - mean * sc;
    }
}

// ---------------------------------------------------------------------------
// Kernel C: in-place normalize + SiLU (4 float4 per thread)
// ---------------------------------------------------------------------------
#define N4TOT ((size_t)BB*COUT*PLANE/4)
#define N4Q   (N4TOT/4)

__global__ __launch_bounds__(256)
void norm_silu(float* __restrict__ y)
{
    const size_t i0 = (size_t)blockIdx.x * 256 + threadIdx.x;
    float4* yp = reinterpret_cast<float4*>(y);
    #pragma unroll
    for (int r = 0; r < 4; r++) {
        size_t idx = i0 + (size_t)r * N4Q;
        int c = (int)((idx >> 14) & 63);
        float sc = g_scale[c];
        float sh = g_shift[c];
        float4 v = yp[idx];
        float t0 = fmaf(v.x, sc, sh);
        float t1 = fmaf(v.y, sc, sh);
        float t2 = fmaf(v.z, sc, sh);
        float t3 = fmaf(v.w, sc, sh);
        v.x = t0 / (1.f + __expf(-t0));
        v.y = t1 / (1.f + __expf(-t1));
        v.z = t2 / (1.f + __expf(-t2));
        v.w = t3 / (1.f + __expf(-t3));
        yp[idx] = v;
    }
}

// ---------------------------------------------------------------------------
extern "C" void kernel_launch(void* const* d_in, const int* in_sizes, int n_in,
                              void* d_out, int out_size)
{
    const float* x      = (const float*)d_in[0];
    const float* w_off  = (const float*)d_in[1];
    const float* b_off  = (const float*)d_in[2];
    const float* w_dcn  = (const float*)d_in[3];
    const float* w_conv = (const float*)d_in[4];
    const float* b_conv = (const float*)d_in[5];
    const float* gamma  = (const float*)d_in[6];
    const float* beta   = (const float*)d_in[7];
    float* out = (float*)d_out;

    cudaFuncSetAttribute(fused_main, cudaFuncAttributeMaxDynamicSharedMemorySize, SMEM_BYTES);

    prep_kernel<<<16, 256>>>(w_off, w_dcn, w_conv);
    fused_main<<<NBLKP, 256, SMEM_BYTES>>>(x, b_off, b_conv, out);
    stats_all<<<16, 256>>>(gamma, beta);
    norm_silu<<<N4Q/256, 256>>>(out);
}

// round 16
// speedup vs baseline: 1.0906x; 1.0906x over previous
#include <cuda_runtime.h>
#include <cuda_fp16.h>
#include <cstdint>

#define BB 16
#define CIN 3
#define HH 256
#define WW 256
#define COUT 64
#define NPIX (BB*HH*WW)
#define PLANE (HH*WW)
#define NBLK (BB*HH)              // 4096 row-blocks

// BN partials: [channel][block]
__device__ float g_partS[COUT * NBLK];
__device__ float g_partQ[COUT * NBLK];
__device__ float g_p2S[COUT * 4];
__device__ float g_p2Q[COUT * 4];
__device__ float g_scale[COUT];
__device__ float g_shift[COUT];

// fp16 intermediate y (134 MB scratch)
__device__ __half g_y[(size_t)NPIX * COUT];

// Pre-packed MMA A-fragments (filled by prep_kernel each launch)
__device__ float4 g_wfragA[7*4*32];   // main GEMM  [kt][m][lane]
__device__ float4 g_wfragO[4*2*32];   // offset GEMM [kt][m][lane]

// ---- dynamic SMEM layout (bytes, 16B aligned) ----
#define TAP_STRIDE 264
#define OFF_WA    0                               // float4[896]       14336
#define OFF_TAPS  (OFF_WA + 896*16)               // float[56][264]    59136
#define OFF_X     (OFF_TAPS + 56*TAP_STRIDE*4)    // float[9][264]      9504
#define OFF_OFFW  (OFF_X + 9*264*4)               // float[8][18][32]  18432
#define OFF_WOFFA (OFF_OFFW + 8*18*32*4)          // float4[256]        4096
#define OFF_BIAS  (OFF_WOFFA + 256*16)            // float[64]           256
#define OFF_REDS  (OFF_BIAS + 64*4)               // float[64][8]       2048
#define OFF_REDQ  (OFF_REDS + 64*8*4)             // float[64][8]       2048
#define SMEM_BYTES (OFF_REDQ + 64*8*4)            // = 109856

__device__ __forceinline__ float tf32r(float f) {
    unsigned u; asm("cvt.rna.tf32.f32 %0, %1;" : "=r"(u) : "f"(f));
    return __uint_as_float(u);
}
__device__ __forceinline__ void mma_tf32(float* d, const unsigned* a, const unsigned* b) {
    asm("mma.sync.aligned.m16n8k8.row.col.f32.tf32.tf32.f32 "
        "{%0,%1,%2,%3}, {%4,%5,%6,%7}, {%8,%9}, {%0,%1,%2,%3};"
        : "+f"(d[0]), "+f"(d[1]), "+f"(d[2]), "+f"(d[3])
        : "r"(a[0]), "r"(a[1]), "r"(a[2]), "r"(a[3]), "r"(b[0]), "r"(b[1]));
}

// ---------------------------------------------------------------------------
// Prep: pack weights into fragment order
// ---------------------------------------------------------------------------
__global__ void prep_kernel(const float* __restrict__ w_off,
                            const float* __restrict__ w_dcn,
                            const float* __restrict__ w_conv)
{
    const int i = blockIdx.x * 256 + threadIdx.x;
    if (i < 3584) {
        int j    = i & 3;
        int lane = (i >> 2) & 31;
        int m    = (i >> 7) & 3;
        int kt   = i >> 9;
        int gg   = lane >> 2, qq = lane & 3;
        int c = m*16 + gg + ((j & 1) << 3);
        int k = kt*8 + qq + ((j >> 1) << 2);
        float v = 0.f;
        if (k < 27)      v = w_conv[c*27 + k];
        else if (k < 54) v = w_dcn[c*27 + (k - 27)];
        reinterpret_cast<float*>(g_wfragA)[i] = tf32r(v);
    }
    if (i < 1024) {
        int j    = i & 3;
        int lane = (i >> 2) & 31;
        int m    = (i >> 7) & 1;
        int kt   = i >> 8;
        int gg   = lane >> 2, qq = lane & 3;
        int c = m*16 + gg + ((j & 1) << 3);
        int k = kt*8 + qq + ((j >> 1) << 2);
        float v = 0.f;
        if (c < 18 && k < 27) v = w_off[c*27 + k];
        reinterpret_cast<float*>(g_wfragO)[i] = tf32r(v);
    }
}

// ---------------------------------------------------------------------------
// Kernel A: warp-pipelined (R13/R9 structure), fp16 y stores.
// ---------------------------------------------------------------------------
__global__ __launch_bounds__(256, 2)
void fused_main(const float* __restrict__ x,
                const float* __restrict__ b_off,
                const float* __restrict__ b_conv)
{
    extern __shared__ __align__(16) char smem[];
    float4* s_wA    = (float4*)(smem + OFF_WA);
    float*  s_taps  = (float*)(smem + OFF_TAPS);
    float*  s_x     = (float*)(smem + OFF_X);
    float*  s_offw  = (float*)(smem + OFF_OFFW);
    float4* s_woffA = (float4*)(smem + OFF_WOFFA);
    float*  s_bias  = (float*)(smem + OFF_BIAS);
    float*  s_redS  = (float*)(smem + OFF_REDS);
    float*  s_redQ  = (float*)(smem + OFF_REDQ);
    __shared__ float s_boff[18];

    const int tid  = threadIdx.x;
    const int bidx = blockIdx.x;
    const int b    = bidx >> 8;
    const int h    = bidx & 255;

    // ---- weight staging ----
    {
        #pragma unroll
        for (int r = 0; r < 4; r++) {
            int i = r*256 + tid;
            if (i < 896) s_wA[i] = g_wfragA[i];
        }
        s_woffA[tid] = g_wfragO[tid];
    }
    // zero tap rows 27..31 and 54..55
    {
        float4* t1 = reinterpret_cast<float4*>(s_taps + 27*TAP_STRIDE);
        for (int i = tid; i < (5*TAP_STRIDE)/4; i += 256) t1[i] = make_float4(0.f,0.f,0.f,0.f);
        float4* t2 = reinterpret_cast<float4*>(s_taps + 54*TAP_STRIDE);
        if (tid < (2*TAP_STRIDE)/4) t2[tid] = make_float4(0.f,0.f,0.f,0.f);
    }
    if (tid < 64) s_bias[tid] = b_conv[tid];
    if (tid < 18) s_boff[tid] = b_off[tid];

    // ---- x staging: 9 rows, thread = column ----
    {
        const float* xb = x + (size_t)b * 3 * PLANE;
        #pragma unroll
        for (int ci = 0; ci < 3; ci++) {
            #pragma unroll
            for (int r = 0; r < 3; r++) {
                const int gy = h - 1 + r;
                const bool rowok = (gy >= 0) && (gy < HH);
                const float* row = xb + ci*PLANE + gy*WW;
                float* dst = s_x + (ci*3 + r)*264;
                int gx = tid - 1;
                dst[tid] = (rowok && gx >= 0) ? row[gx] : 0.f;
                if (tid < 2) {
                    int gx2 = 255 + tid;
                    dst[256 + tid] = (rowok && gx2 < WW) ? row[gx2] : 0.f;
                }
            }
        }
    }
    __syncthreads();   // only block-wide sync before epilogue

    const int wid  = tid >> 5;
    const int lane = tid & 31;
    const int g    = lane >> 2;
    const int q    = lane & 3;
    const int pxw  = wid << 5;
    float* offw    = s_offw + wid * (18*32);

    // ---- im2col: thread w writes tf32 tap column w, rows 0..26 ----
    {
        const int w = tid;
        #pragma unroll
        for (int ci = 0; ci < 3; ci++)
            #pragma unroll
            for (int k = 0; k < 9; k++)
                s_taps[(ci*9 + k)*TAP_STRIDE + w] =
                    tf32r(s_x[(ci*3 + k/3)*264 + w + (k%3)]);
    }
    __syncwarp();

    // ================= Offset conv MMA (warp-local) =================
    {
        float Co[2][4][4];
        #pragma unroll
        for (int m = 0; m < 2; m++)
            #pragma unroll
            for (int n = 0; n < 4; n++)
                #pragma unroll
                for (int r = 0; r < 4; r++) Co[m][n][r] = 0.f;

        #pragma unroll
        for (int kt = 0; kt < 4; kt++) {
            const int kb = kt << 3;
            unsigned A[2][4];
            #pragma unroll
            for (int m = 0; m < 2; m++) {
                float4 af = s_woffA[(kt*2 + m)*32 + lane];
                A[m][0] = __float_as_uint(af.x);
                A[m][1] = __float_as_uint(af.y);
                A[m][2] = __float_as_uint(af.z);
                A[m][3] = __float_as_uint(af.w);
            }
            unsigned Bf[4][2];
            #pragma unroll
            for (int n = 0; n < 4; n++) {
                const float* bp = s_taps + (kb + q)*TAP_STRIDE + pxw + (n << 3) + g;
                Bf[n][0] = __float_as_uint(bp[0]);
                Bf[n][1] = __float_as_uint(bp[4*TAP_STRIDE]);
            }
            #pragma unroll
            for (int m = 0; m < 2; m++)
                #pragma unroll
                for (int n = 0; n < 4; n++)
                    mma_tf32(Co[m][n], A[m], Bf[n]);
        }

        #pragma unroll
        for (int n = 0; n < 4; n++) {
            const int cw = (n << 3) + (q << 1);
            *reinterpret_cast<float2*>(offw + g*32 + cw)
                = make_float2(Co[0][n][0], Co[0][n][1]);
            *reinterpret_cast<float2*>(offw + (g+8)*32 + cw)
                = make_float2(Co[0][n][2], Co[0][n][3]);
            if (g < 2)
                *reinterpret_cast<float2*>(offw + (16+g)*32 + cw)
                    = make_float2(Co[1][n][0], Co[1][n][1]);
        }
    }
    __syncwarp();

    // ================= Gathers: deform taps rows 27..53 (warp-local) ========
    {
        const int w = tid;
        const float* xb = x + (size_t)b * 3 * PLANE;
        #pragma unroll
        for (int k = 0; k < 9; k++) {
            float dy = offw[(2*k)*32 + lane]   + s_boff[2*k];
            float dx = offw[(2*k+1)*32 + lane] + s_boff[2*k+1];
            const int ky = k / 3, kx = k - 3*ky;
            float py = (float)(h + ky - 1) + dy;
            float px = (float)(w + kx - 1) + dx;
            float y0 = floorf(py), x0 = floorf(px);
            float ly = py - y0,    lx = px - x0;
            float hy = 1.f - ly,   hx = 1.f - lx;
            float y1 = y0 + 1.f,   x1 = x0 + 1.f;
            bool vy0 = (y0 >= 0.f) && (y0 <= 255.f);
            bool vy1 = (y1 >= 0.f) && (y1 <= 255.f);
            bool vx0 = (x0 >= 0.f) && (x0 <= 255.f);
            bool vx1 = (x1 >= 0.f) && (x1 <= 255.f);
            float w00 = hy*hx * ((vy0 && vx0) ? 1.f : 0.f);
            float w01 = hy*lx * ((vy0 && vx1) ? 1.f : 0.f);
            float w10 = ly*hx * ((vy1 && vx0) ? 1.f : 0.f);
            float w11 = ly*lx * ((vy1 && vx1) ? 1.f : 0.f);
            int iy0 = min(max((int)y0, 0), 255);
            int iy1 = min(max((int)y1, 0), 255);
            int ix0 = min(max((int)x0, 0), 255);
            int ix1 = min(max((int)x1, 0), 255);
            int i00 = iy0*WW + ix0, i01 = iy0*WW + ix1;
            int i10 = iy1*WW + ix0, i11 = iy1*WW + ix1;
            #pragma unroll
            for (int ci = 0; ci < 3; ci++) {
                const float* xc = xb + ci * PLANE;
                float tap = w00 * __ldg(xc + i00) + w01 * __ldg(xc + i01)
                          + w10 * __ldg(xc + i10) + w11 * __ldg(xc + i11);
                s_taps[(27 + ci*9 + k)*TAP_STRIDE + w] = tf32r(tap);
            }
        }
    }
    __syncwarp();

    // ================= Main tensor-core GEMM (warp-local) ==================
    float C[4][4][4];
    #pragma unroll
    for (int m = 0; m < 4; m++)
        #pragma unroll
        for (int n = 0; n < 4; n++)
            #pragma unroll
            for (int r = 0; r < 4; r++) C[m][n][r] = 0.f;

    #pragma unroll
    for (int kt = 0; kt < 7; kt++) {
        const int kb = kt << 3;
        unsigned A[4][4];
        #pragma unroll
        for (int m = 0; m < 4; m++) {
            float4 af = s_wA[(kt*4 + m)*32 + lane];
            A[m][0] = __float_as_uint(af.x);
            A[m][1] = __float_as_uint(af.y);
            A[m][2] = __float_as_uint(af.z);
            A[m][3] = __float_as_uint(af.w);
        }
        unsigned Bf[4][2];
        #pragma unroll
        for (int n = 0; n < 4; n++) {
            const float* bp = s_taps + (kb + q)*TAP_STRIDE + pxw + (n << 3) + g;
            Bf[n][0] = __float_as_uint(bp[0]);
            Bf[n][1] = __float_as_uint(bp[4*TAP_STRIDE]);
        }
        #pragma unroll
        for (int m = 0; m < 4; m++)
            #pragma unroll
            for (int n = 0; n < 4; n++)
                mma_tf32(C[m][n], A[m], Bf[n]);
    }

    // ---- epilogue: bias, fp16 store, BN partials ----
    __half* ybh = g_y + (size_t)b * COUT * PLANE + (size_t)h * WW;
    #pragma unroll
    for (int m = 0; m < 4; m++) {
        const int ch0 = m*16 + g;
        const int ch1 = ch0 + 8;
        const float b0v = s_bias[ch0];
        const float b1v = s_bias[ch1];
        float s0 = 0.f, q0 = 0.f, s1 = 0.f, q1 = 0.f;
        #pragma unroll
        for (int n = 0; n < 4; n++) {
            float c0 = C[m][n][0] + b0v, c1 = C[m][n][1] + b0v;
            float c2 = C[m][n][2] + b1v, c3 = C[m][n][3] + b1v;
            const int px = pxw + (n << 3) + (q << 1);
            *reinterpret_cast<__half2*>(ybh + (size_t)ch0 * PLANE + px)
                = __float22half2_rn(make_float2(c0, c1));
            *reinterpret_cast<__half2*>(ybh + (size_t)ch1 * PLANE + px)
                = __float22half2_rn(make_float2(c2, c3));
            s0 += c0 + c1;  q0 += c0*c0 + c1*c1;
            s1 += c2 + c3;  q1 += c2*c2 + c3*c3;
        }
        #pragma unroll
        for (int d = 1; d < 4; d <<= 1) {
            s0 += __shfl_xor_sync(0xffffffffu, s0, d);
            q0 += __shfl_xor_sync(0xffffffffu, q0, d);
            s1 += __shfl_xor_sync(0xffffffffu, s1, d);
            q1 += __shfl_xor_sync(0xffffffffu, q1, d);
        }
        if (q == 0) {
            s_redS[ch0*8 + wid] = s0;  s_redQ[ch0*8 + wid] = q0;
            s_redS[ch1*8 + wid] = s1;  s_redQ[ch1*8 + wid] = q1;
        }
    }
    __syncthreads();

    if (tid < COUT) {
        float s = 0.f, qq = 0.f;
        #pragma unroll
        for (int wdx = 0; wdx < 8; wdx++) {
            s  += s_redS[tid*8 + wdx];
            qq += s_redQ[tid*8 + wdx];
        }
        g_partS[tid*NBLK + bidx] = s;
        g_partQ[tid*NBLK + bidx] = qq;
    }
}

// ---------------------------------------------------------------------------
// Kernel B1: partial stats reduce — 4 blocks per channel, float4 loads
// ---------------------------------------------------------------------------
__global__ __launch_bounds__(256)
void stats_part()
{
    const int bc  = blockIdx.x;          // c*4 + quarter
    const int c   = bc >> 2;
    const int qtr = bc & 3;
    const float4* ps = reinterpret_cast<const float4*>(g_partS + c*NBLK + qtr*1024);
    const float4* pq = reinterpret_cast<const float4*>(g_partQ + c*NBLK + qtr*1024);
    const int tid = threadIdx.x;
    float4 a = ps[tid];
    float4 d = pq[tid];
    float s = (a.x + a.y) + (a.z + a.w);
    float q = (d.x + d.y) + (d.z + d.w);
    #pragma unroll
    for (int off = 16; off > 0; off >>= 1) {
        s += __shfl_xor_sync(0xffffffffu, s, off);
        q += __shfl_xor_sync(0xffffffffu, q, off);
    }
    __shared__ float ss[8], sq[8];
    if ((tid & 31) == 0) { ss[tid >> 5] = s; sq[tid >> 5] = q; }
    __syncthreads();
    if (tid == 0) {
        float S = 0.f, Q = 0.f;
        #pragma unroll
        for (int i = 0; i < 8; i++) { S += ss[i]; Q += sq[i]; }
        g_p2S[bc] = S;
        g_p2Q[bc] = Q;
    }
}

// ---------------------------------------------------------------------------
// Kernel B2: finalize scale/shift
// ---------------------------------------------------------------------------
__global__ void stats_fin(const float* __restrict__ gamma,
                          const float* __restrict__ beta)
{
    const int c = threadIdx.x;
    if (c >= COUT) return;
    float s = g_p2S[c*4] + g_p2S[c*4+1] + g_p2S[c*4+2] + g_p2S[c*4+3];
    float q = g_p2Q[c*4] + g_p2Q[c*4+1] + g_p2Q[c*4+2] + g_p2Q[c*4+3];
    const float invN = 1.f / (float)NPIX;
    float mean = s * invN;
    float var  = q * invN - mean * mean;
    float inv  = rsqrtf(var + 1e-5f);
    float sc   = gamma[c] * inv;
    g_scale[c] = sc;
    g_shift[c] = beta[c] - mean * sc;
}

// ---------------------------------------------------------------------------
// Kernel C: fp16 y -> normalize + SiLU -> fp32 out (4 elems x 4 iters/thread)
// ---------------------------------------------------------------------------
#define N4TOT ((size_t)BB*COUT*PLANE/4)
#define N4Q   (N4TOT/4)

__global__ __launch_bounds__(256)
void norm_silu(float* __restrict__ out)
{
    const size_t i0 = (size_t)blockIdx.x * 256 + threadIdx.x;
    float4* op = reinterpret_cast<float4*>(out);
    #pragma unroll
    for (int r = 0; r < 4; r++) {
        size_t idx = i0 + (size_t)r * N4Q;     // float4/4-element index
        int c = (int)((idx >> 14) & 63);
        float sc = g_scale[c];
        float sh = g_shift[c];
        uint2 hv = *reinterpret_cast<const uint2*>(g_y + idx*4);
        __half2 ha = *reinterpret_cast<__half2*>(&hv.x);
        __half2 hb = *reinterpret_cast<__half2*>(&hv.y);
        float2 fa = __half22float2(ha);
        float2 fb = __half22float2(hb);
        float t0 = fmaf(fa.x, sc, sh);
        float t1 = fmaf(fa.y, sc, sh);
        float t2 = fmaf(fb.x, sc, sh);
        float t3 = fmaf(fb.y, sc, sh);
        float4 v;
        v.x = t0 / (1.f + __expf(-t0));
        v.y = t1 / (1.f + __expf(-t1));
        v.z = t2 / (1.f + __expf(-t2));
        v.w = t3 / (1.f + __expf(-t3));
        op[idx] = v;
    }
}

// ---------------------------------------------------------------------------
extern "C" void kernel_launch(void* const* d_in, const int* in_sizes, int n_in,
                              void* d_out, int out_size)
{
    const float* x      = (const float*)d_in[0];
    const float* w_off  = (const float*)d_in[1];
    const float* b_off  = (const float*)d_in[2];
    const float* w_dcn  = (const float*)d_in[3];
    const float* w_conv = (const float*)d_in[4];
    const float* b_conv = (const float*)d_in[5];
    const float* gamma  = (const float*)d_in[6];
    const float* beta   = (const float*)d_in[7];
    float* out = (float*)d_out;

    cudaFuncSetAttribute(fused_main, cudaFuncAttributeMaxDynamicSharedMemorySize, SMEM_BYTES);

    prep_kernel<<<16, 256>>>(w_off, w_dcn, w_conv);
    fused_main<<<NBLK, 256, SMEM_BYTES>>>(x, b_off, b_conv);
    stats_part<<<COUT*4, 256>>>();
    stats_fin<<<1, 64>>>(gamma, beta);
    norm_silu<<<N4Q/256, 256>>>(out);
}